// round 12
// baseline (speedup 1.0000x reference)
#include <cuda_runtime.h>
#include <cuda_bf16.h>
#include <math.h>
#include <stdint.h>

// Problem dims
#define NB   32
#define NTX  128
#define NTY  64
#define NV   50000
#define ND   128
#define NH   256
#define NG4  1024
#define NSTEPS (NTX + NTY)

// LSTM partitioning: 4 independent groups x 32 blocks
#define NGR   4      // groups (8 batches each)
#define BPG   32     // blocks per group (8 units each)
#define BATG  8      // batches per group
#define NBLK  (NGR * BPG)   // 128

// lstm dynamic smem layout (bytes)
//  [0,65536)       h-part weights: [mat][128 kp][32 cols] float2
//  [65536,98304)   x-part weights: [mat][64 kp][32 cols] float2
//  [98304,106496)  psum: [8 warps][8 c][32 lane] float
#define LWH_OFF   0
#define LWX_OFF   65536
#define LPS_OFF   98304
#define LSTM_SMEM 106496

// Projection tiling
#define MT   128
#define NT   128
#define NMT  16
#define NNT  ((NV + NT - 1) / NT)     // 391
#define NGP  9                        // 144 CTAs, single wave

// proj smem layout (bytes)
#define APITCH    528
#define ASPLIT    (128 * APITCH)
#define B_OFF     (2 * ASPLIT)
#define BROWP     80
#define BSEG      (32 * BROWP)
#define BWARP     (4 * BSEG)
#define PROJ_SMEM (B_OFF + 8 * BWARP) // 217088

// ---------------- scratch (device globals) ----------------------------------
__device__ float g_ht2[2 * NGR * NH * BATG];   // [p][g][u][bt]
__device__ int   g_bar[NBLK * 32];             // one flag per 128B line
__device__ __align__(16) __nv_bfloat16 g_hsh[NTY * NB * NH];
__device__ __align__(16) __nv_bfloat16 g_hsl[NTY * NB * NH];
__device__ __align__(16) __nv_bfloat16 g_wth[(long)NV * NH];
__device__ __align__(16) __nv_bfloat16 g_wtl[(long)NV * NH];

// ---------------- helpers ----------------------------------------------------
__device__ __forceinline__ uint32_t smem_u32(const void* p) {
    uint32_t a;
    asm("{ .reg .u64 t; cvta.to.shared.u64 t, %1; cvt.u32.u64 %0, t; }"
        : "=r"(a) : "l"(p));
    return a;
}
__device__ __forceinline__ void ldsm4(uint32_t* r, uint32_t addr) {
    asm volatile("ldmatrix.sync.aligned.m8n8.x4.shared.b16 {%0,%1,%2,%3}, [%4];"
                 : "=r"(r[0]), "=r"(r[1]), "=r"(r[2]), "=r"(r[3]) : "r"(addr));
}
__device__ __forceinline__ void mma16816(float* c, const uint32_t* a,
                                         const uint32_t* b) {
    asm volatile(
        "mma.sync.aligned.m16n8k16.row.col.f32.bf16.bf16.f32 "
        "{%0,%1,%2,%3}, {%4,%5,%6,%7}, {%8,%9}, {%0,%1,%2,%3};"
        : "+f"(c[0]), "+f"(c[1]), "+f"(c[2]), "+f"(c[3])
        : "r"(a[0]), "r"(a[1]), "r"(a[2]), "r"(a[3]), "r"(b[0]), "r"(b[1]));
}
__device__ __forceinline__ void cp16(uint32_t dst, const void* src, int sz) {
    asm volatile("cp.async.cg.shared.global [%0], [%1], 16, %2;"
                 :: "r"(dst), "l"(src), "r"(sz));
}
__device__ __forceinline__ float sigm(float x) { return 1.f / (1.f + expf(-x)); }
__device__ __forceinline__ int ld_acq(const int* p) {
    int v; asm volatile("ld.acquire.gpu.global.s32 %0, [%1];" : "=r"(v) : "l"(p)); return v;
}
__device__ __forceinline__ void st_rel(int* p, int v) {
    asm volatile("st.release.gpu.global.s32 [%0], %1;" :: "l"(p), "r"(v) : "memory");
}

__global__ void init_state() {
    int i = blockIdx.x * blockDim.x + threadIdx.x;
    if (i < 2 * NGR * NH * BATG) g_ht2[i] = 0.f;
    if (i < NBLK * 32)           g_bar[i] = 0;
}

// ---------------- W_proj transpose + bf16 hi/lo split ------------------------
__global__ void __launch_bounds__(256) wsplit(const float* __restrict__ W) {
    __shared__ float tile[32][33];
    int v0 = blockIdx.x * 32, k0 = blockIdx.y * 32;
    int tx = threadIdx.x & 31, ty = threadIdx.x >> 5;
    #pragma unroll
    for (int i = 0; i < 4; i++) {
        int k = k0 + ty + i * 8, v = v0 + tx;
        tile[ty + i * 8][tx] = (v < NV) ? W[(long)k * NV + v] : 0.f;
    }
    __syncthreads();
    #pragma unroll
    for (int i = 0; i < 4; i++) {
        int v = v0 + ty + i * 8;
        if (v < NV) {
            float x = tile[tx][ty + i * 8];
            __nv_bfloat16 h = __float2bfloat16(x);
            float r = x - __bfloat162float(h);
            g_wth[(long)v * NH + k0 + tx] = h;
            g_wtl[(long)v * NH + k0 + tx] = __float2bfloat16(r);
        }
    }
}

// ---------------- persistent LSTM: 4 groups x 32 blocks ----------------------
// Group g handles batches 8g..8g+7 (fully independent recurrences).
// Block j in group owns units j*8..j*8+7 => 32 gate cols for 8 batches.
// Lane = (batch = lane>>2, colq = lane&3: 8 cols). Warp w: h k-slice
// [32w,32w+32), x k-slice [16w,16w+16). Sync: 32 spread flags per group.
extern __shared__ __align__(16) char lsm[];
__global__ void __launch_bounds__(256, 1) lstm_persist(
    const int* __restrict__ enc_in, const int* __restrict__ dec_in,
    const float* __restrict__ E,
    const float* __restrict__ W_enc, const float* __restrict__ b_enc,
    const float* __restrict__ W_dec, const float* __restrict__ b_dec,
    const int* __restrict__ len)
{
    int tid  = threadIdx.x;
    int bk   = blockIdx.x;
    int g    = bk >> 5;          // group
    int j    = bk & 31;          // block within group
    int lane = tid & 31;
    int w    = tid >> 5;
    int u0   = j * 8;
    int batl = lane >> 2;        // batch within group (0..7)
    int colq = lane & 3;         // col quad (8 cols each)

    // ---- load weight slices into dynamic smem ----
    // h-part: [mat][kp 0..127][col 0..31] float2 (k-pair per col)
    for (int idx = tid; idx < 4096; idx += 256) {
        int k2 = idx >> 5, cl = idx & 31;
        int gcol = (cl >> 3) * NH + u0 + (cl & 7);
        float2 ve = make_float2(W_enc[(long)(ND + 2 * k2) * NG4 + gcol],
                                W_enc[(long)(ND + 2 * k2 + 1) * NG4 + gcol]);
        float2 vd = make_float2(W_dec[(long)(ND + 2 * k2) * NG4 + gcol],
                                W_dec[(long)(ND + 2 * k2 + 1) * NG4 + gcol]);
        *reinterpret_cast<float2*>(lsm + LWH_OFF + k2 * 256 + cl * 8) = ve;
        *reinterpret_cast<float2*>(lsm + LWH_OFF + 32768 + k2 * 256 + cl * 8) = vd;
    }
    // x-part: [mat][kp 0..63][col 0..31] float2
    for (int idx = tid; idx < 2048; idx += 256) {
        int k2 = idx >> 5, cl = idx & 31;
        int gcol = (cl >> 3) * NH + u0 + (cl & 7);
        float2 ve = make_float2(W_enc[(long)(2 * k2) * NG4 + gcol],
                                W_enc[(long)(2 * k2 + 1) * NG4 + gcol]);
        float2 vd = make_float2(W_dec[(long)(2 * k2) * NG4 + gcol],
                                W_dec[(long)(2 * k2 + 1) * NG4 + gcol]);
        *reinterpret_cast<float2*>(lsm + LWX_OFF + k2 * 256 + cl * 8) = ve;
        *reinterpret_cast<float2*>(lsm + LWX_OFF + 16384 + k2 * 256 + cl * 8) = vd;
    }
    float* psum = reinterpret_cast<float*>(lsm + LPS_OFF);

    // ---- persistent state: finalize thread (tid<64) = (unit iu, batch bt) ----
    int iu = tid >> 3, bt = tid & 7;     // valid for tid<64
    float creg = 0.f, hreg = 0.f;
    int mylen = 0;
    float be[4] = {0, 0, 0, 0}, bd[4] = {0, 0, 0, 0};
    if (tid < 64) {
        mylen = len[g * BATG + bt];
        int u = u0 + iu;
        #pragma unroll
        for (int q = 0; q < 4; q++) {
            be[q] = b_enc[q * NH + u];
            bd[q] = b_dec[q * NH + u];
        }
    }

    __syncthreads();

    for (int s = 0; s < NSTEPS; s++) {
        int p = s & 1;
        int is_enc = (s < NTX);
        int t = is_enc ? s : s - NTX;

        // ---- embedding gather (issued before poll; hidden by the wait) ----
        const int* toks = is_enc ? enc_in : dec_in;
        int T = is_enc ? NTX : NTY;
        int tokb = __ldg(&toks[(g * BATG + batl) * T + t]);
        float ev[16];
        {
            const float4* er = reinterpret_cast<const float4*>(
                E + (long)tokb * ND + w * 16);
            float4 e0 = __ldg(er), e1 = __ldg(er + 1);
            float4 e2 = __ldg(er + 2), e3 = __ldg(er + 3);
            ev[0]=e0.x; ev[1]=e0.y; ev[2]=e0.z; ev[3]=e0.w;
            ev[4]=e1.x; ev[5]=e1.y; ev[6]=e1.z; ev[7]=e1.w;
            ev[8]=e2.x; ev[9]=e2.y; ev[10]=e2.z; ev[11]=e2.w;
            ev[12]=e3.x; ev[13]=e3.y; ev[14]=e3.z; ev[15]=e3.w;
        }

        // ---- group barrier: wait for own group's 32 blocks at step s-1 ----
        if (s > 0) {
            if (tid < BPG) {
                const int* f = &g_bar[((g << 5) + tid) * 32];
                while (ld_acq(f) < s) { __nanosleep(32); }
            }
            __syncthreads();
        }

        // ---- x-part FMAs ----
        unsigned long long acc2[8];
        #pragma unroll
        for (int c = 0; c < 8; c++) acc2[c] = 0ull;

        const ulonglong2* xrow = reinterpret_cast<const ulonglong2*>(
            lsm + LWX_OFF + (is_enc ? 0 : 16384));
        #pragma unroll
        for (int kp = 0; kp < 8; kp++) {
            unsigned long long a2;
            asm("mov.b64 %0, {%1, %2};" : "=l"(a2)
                : "f"(ev[2 * kp]), "f"(ev[2 * kp + 1]));
            int base = (w * 8 + kp) * 16 + colq * 4;
            #pragma unroll
            for (int q = 0; q < 4; q++) {
                ulonglong2 qq = xrow[base + q];
                asm("fma.rn.f32x2 %0, %1, %2, %3;"
                    : "=l"(acc2[2 * q]) : "l"(a2), "l"(qq.x), "l"(acc2[2 * q]));
                asm("fma.rn.f32x2 %0, %1, %2, %3;"
                    : "=l"(acc2[2 * q + 1]) : "l"(a2), "l"(qq.y), "l"(acc2[2 * q + 1]));
            }
        }

        // ---- h loads: [p][g][u][bt], 1 sector per k ----
        const float* hsrc = g_ht2 + ((long)p * NGR + g) * NH * BATG;
        float hv[32];
        #pragma unroll
        for (int k = 0; k < 32; k++)
            hv[k] = __ldcg(hsrc + (w * 32 + k) * BATG + batl);

        const ulonglong2* wrow = reinterpret_cast<const ulonglong2*>(
            lsm + LWH_OFF + (is_enc ? 0 : 32768));
        #pragma unroll
        for (int kp = 0; kp < 16; kp++) {
            unsigned long long a2;
            asm("mov.b64 %0, {%1, %2};" : "=l"(a2)
                : "f"(hv[2 * kp]), "f"(hv[2 * kp + 1]));
            int base = (w * 16 + kp) * 16 + colq * 4;
            #pragma unroll
            for (int q = 0; q < 4; q++) {
                ulonglong2 qq = wrow[base + q];
                asm("fma.rn.f32x2 %0, %1, %2, %3;"
                    : "=l"(acc2[2 * q]) : "l"(a2), "l"(qq.x), "l"(acc2[2 * q]));
                asm("fma.rn.f32x2 %0, %1, %2, %3;"
                    : "=l"(acc2[2 * q + 1]) : "l"(a2), "l"(qq.y), "l"(acc2[2 * q + 1]));
            }
        }
        // psum[w][c][lane]: col = colq*8 + c, batch = batl
        #pragma unroll
        for (int c = 0; c < 8; c++) {
            float lo = __uint_as_float((unsigned)(acc2[c] & 0xffffffffull));
            float hi = __uint_as_float((unsigned)(acc2[c] >> 32));
            psum[w * 256 + c * 32 + lane] = lo + hi;
        }
        __syncthreads();

        // ---- finalize: 64 threads = (iu, bt) ----
        if (tid < 64) {
            // gate q partial lives at lane = bt*4 + q, c = iu
            float z[4];
            #pragma unroll
            for (int q = 0; q < 4; q++)
                z[q] = is_enc ? be[q] : bd[q];
            #pragma unroll
            for (int ww = 0; ww < 8; ww++) {
                #pragma unroll
                for (int q = 0; q < 4; q++)
                    z[q] += psum[ww * 256 + iu * 32 + bt * 4 + q];
            }
            float nc = creg * sigm(z[2] + 1.f) + sigm(z[0]) * tanhf(z[1]);
            float nh = tanhf(nc) * sigm(z[3]);
            if (is_enc && t >= mylen) { nc = creg; nh = hreg; }
            creg = nc; hreg = nh;
            int u = u0 + iu;
            g_ht2[(((long)(p ^ 1) * NGR + g) * NH + u) * BATG + bt] = nh;
            if (!is_enc) {
                __nv_bfloat16 hh = __float2bfloat16(nh);
                float rr = nh - __bfloat162float(hh);
                long mrow = (long)t * NB + g * BATG + bt;
                g_hsh[mrow * NH + u] = hh;
                g_hsl[mrow * NH + u] = __float2bfloat16(rr);
            }
        }
        __syncthreads();
        if (tid == 0) st_rel(&g_bar[bk * 32], s + 1);
    }
}

// ---------------- projection: warp-private B pipeline (round-9 proven) ------
extern __shared__ __align__(16) char proj_sm[];
__global__ void __launch_bounds__(256, 1) proj_mma(float* __restrict__ out)
{
    uint32_t sbase = smem_u32(proj_sm);
    int tid  = threadIdx.x;
    int lane = tid & 31;
    int wid  = tid >> 5;
    int wm   = wid >> 2;
    int wn   = wid & 3;
    int row0 = blockIdx.x * MT;
    int ng   = blockIdx.y;

    for (int i = tid; i < 8192; i += 256) {
        int s = i >> 12, w = i & 4095, row = w >> 5, kseg = w & 31;
        const __nv_bfloat16* src = s ? g_hsl : g_hsh;
        uint4 v = *reinterpret_cast<const uint4*>(
            src + (long)(row0 + row) * NH + kseg * 8);
        *reinterpret_cast<uint4*>(proj_sm + s * ASPLIT + row * APITCH + kseg * 16) = v;
    }
    __syncthreads();

    uint32_t aBase = sbase + (wm * 64 + (lane & 15)) * APITCH + ((lane >> 4) * 8) * 2;
    uint32_t warpB = sbase + B_OFF + wid * BWARP;
    uint32_t bThr  = ((lane & 7) + ((lane >> 4) << 3)) * BROWP
                   + (((lane >> 3) & 1) * 8) * 2;

    for (int nt = ng; nt < NNT; nt += NGP) {
        int col0 = nt * NT;
        int vbase = col0 + wn * 32;

        float acc[4][4][4];
        #pragma unroll
        for (int a = 0; a < 4; a++)
            #pragma unroll
            for (int b = 0; b < 4; b++)
                #pragma unroll
                for (int c = 0; c < 4; c++) acc[a][b][c] = 0.f;

        auto loadB = [&](int c, int buf) {
            #pragma unroll
            for (int q = 0; q < 8; q++) {
                int s = q >> 2;
                int i = lane + 32 * (q & 3);
                int row = i >> 2, seg = i & 3;
                int gv = vbase + row;
                int cgv = gv < NV ? gv : NV - 1;
                const __nv_bfloat16* src =
                    (s ? g_wtl : g_wth) + (long)cgv * NH + c * 32 + seg * 8;
                uint32_t dst = warpB + buf * (2 * BSEG) + s * BSEG
                             + row * BROWP + seg * 16;
                cp16(dst, src, gv < NV ? 16 : 0);
            }
            asm volatile("cp.async.commit_group;" ::: "memory");
        };

        loadB(0, 0);
        loadB(1, 1);

        #pragma unroll 1
        for (int c = 0; c < 8; c++) {
            if (c == 7) { asm volatile("cp.async.wait_group 0;" ::: "memory"); }
            else        { asm volatile("cp.async.wait_group 1;" ::: "memory"); }
            __syncwarp();

            int buf = c & 1;
            uint32_t bufH = warpB + buf * (2 * BSEG) + bThr;
            uint32_t bufL = bufH + BSEG;

            #pragma unroll
            for (int kk = 0; kk < 2; kk++) {
                int kg = c * 32 + kk * 16;
                int kl = kk * 32;
                uint32_t ah[4][4], al[4][4];
                #pragma unroll
                for (int mt = 0; mt < 4; mt++) {
                    ldsm4(ah[mt], aBase + mt * (16 * APITCH) + kg * 2);
                    ldsm4(al[mt], aBase + ASPLIT + mt * (16 * APITCH) + kg * 2);
                }
                uint32_t bh[2][4], bl[2][4];
                #pragma unroll
                for (int l = 0; l < 2; l++) {
                    ldsm4(bh[l], bufH + l * (16 * BROWP) + kl);
                    ldsm4(bl[l], bufL + l * (16 * BROWP) + kl);
                }
                #pragma unroll
                for (int mt = 0; mt < 4; mt++) {
                    #pragma unroll
                    for (int ntl = 0; ntl < 4; ntl++) {
                        int l = ntl >> 1, p = (ntl & 1) * 2;
                        uint32_t bhf[2] = {bh[l][p], bh[l][p + 1]};
                        uint32_t blf[2] = {bl[l][p], bl[l][p + 1]};
                        mma16816(acc[mt][ntl], ah[mt], bhf);
                        mma16816(acc[mt][ntl], ah[mt], blf);
                        mma16816(acc[mt][ntl], al[mt], bhf);
                    }
                }
            }
            if (c + 2 < 8) loadB(c + 2, buf);
        }

        #pragma unroll
        for (int mt = 0; mt < 4; mt++) {
            int r0 = row0 + wm * 64 + mt * 16 + (lane >> 2);
            int r1 = r0 + 8;
            int tt0 = r0 >> 5, bb0 = r0 & 31;
            int tt1 = r1 >> 5, bb1 = r1 & 31;
            float* o0 = out + (long)bb0 * NTY * NV + (long)tt0 * NV;
            float* o1 = out + (long)bb1 * NTY * NV + (long)tt1 * NV;
            #pragma unroll
            for (int ntl = 0; ntl < 4; ntl++) {
                int cc = vbase + ntl * 8 + 2 * (lane & 3);
                if (cc < NV) {
                    float2 v0 = make_float2(acc[mt][ntl][0], acc[mt][ntl][1]);
                    float2 v1 = make_float2(acc[mt][ntl][2], acc[mt][ntl][3]);
                    *reinterpret_cast<float2*>(o0 + cc) = v0;
                    *reinterpret_cast<float2*>(o1 + cc) = v1;
                }
            }
        }
    }
}

// ---------------- launch ----------------------------------------------------
extern "C" void kernel_launch(void* const* d_in, const int* in_sizes, int n_in,
                              void* d_out, int out_size)
{
    const int*   enc_in = (const int*)d_in[0];
    const int*   dec_in = (const int*)d_in[1];
    const int*   len    = (const int*)d_in[2];
    const float* E      = (const float*)d_in[3];
    const float* W_enc  = (const float*)d_in[4];
    const float* b_enc  = (const float*)d_in[5];
    const float* W_dec  = (const float*)d_in[6];
    const float* b_dec  = (const float*)d_in[7];
    const float* W_proj = (const float*)d_in[8];
    float* out = (float*)d_out;

    cudaFuncSetAttribute(lstm_persist, cudaFuncAttributeMaxDynamicSharedMemorySize,
                         LSTM_SMEM);
    cudaFuncSetAttribute(proj_mma, cudaFuncAttributeMaxDynamicSharedMemorySize,
                         PROJ_SMEM);

    init_state<<<64, 256>>>();

    wsplit<<<dim3((NV + 31) / 32, 8), 256>>>(W_proj);

    lstm_persist<<<NBLK, 256, LSTM_SMEM>>>(enc_in, dec_in, E, W_enc, b_enc,
                                           W_dec, b_dec, len);

    proj_mma<<<dim3(NMT, NGP), 256, PROJ_SMEM>>>(out);
}

// round 13
// speedup vs baseline: 1.2434x; 1.2434x over previous
#include <cuda_runtime.h>
#include <cuda_bf16.h>
#include <math.h>
#include <stdint.h>

// Problem dims
#define NB   32
#define NTX  128
#define NTY  64
#define NV   50000
#define ND   128
#define NH   256
#define NG4  1024
#define NSTEPS (NTX + NTY)
#define NBLK 128

// Projection tiling
#define MT   128
#define NT   128
#define NMT  16
#define NNT  ((NV + NT - 1) / NT)     // 391
#define NGP  9                        // 144 CTAs, single wave

// proj smem layout (bytes from dynamic smem base)
#define APITCH    528
#define ASPLIT    (128 * APITCH)
#define B_OFF     (2 * ASPLIT)
#define BROWP     80
#define BSEG      (32 * BROWP)
#define BWARP     (4 * BSEG)
#define PROJ_SMEM (B_OFF + 8 * BWARP) // 217088

// ---------------- scratch (device globals) ----------------------------------
__device__ float g_ht[2 * NH * NB];
__device__ int   g_bar[NBLK * 32];          // one flag per 128B line (proven)
__device__ __align__(16) __nv_bfloat16 g_hsh[NTY * NB * NH];
__device__ __align__(16) __nv_bfloat16 g_hsl[NTY * NB * NH];
__device__ __align__(16) __nv_bfloat16 g_wth[(long)NV * NH];
__device__ __align__(16) __nv_bfloat16 g_wtl[(long)NV * NH];

// ---------------- helpers ----------------------------------------------------
__device__ __forceinline__ uint32_t smem_u32(const void* p) {
    uint32_t a;
    asm("{ .reg .u64 t; cvta.to.shared.u64 t, %1; cvt.u32.u64 %0, t; }"
        : "=r"(a) : "l"(p));
    return a;
}
__device__ __forceinline__ void ldsm4(uint32_t* r, uint32_t addr) {
    asm volatile("ldmatrix.sync.aligned.m8n8.x4.shared.b16 {%0,%1,%2,%3}, [%4];"
                 : "=r"(r[0]), "=r"(r[1]), "=r"(r[2]), "=r"(r[3]) : "r"(addr));
}
__device__ __forceinline__ void mma16816(float* c, const uint32_t* a,
                                         const uint32_t* b) {
    asm volatile(
        "mma.sync.aligned.m16n8k16.row.col.f32.bf16.bf16.f32 "
        "{%0,%1,%2,%3}, {%4,%5,%6,%7}, {%8,%9}, {%0,%1,%2,%3};"
        : "+f"(c[0]), "+f"(c[1]), "+f"(c[2]), "+f"(c[3])
        : "r"(a[0]), "r"(a[1]), "r"(a[2]), "r"(a[3]), "r"(b[0]), "r"(b[1]));
}
__device__ __forceinline__ void cp16(uint32_t dst, const void* src, int sz) {
    asm volatile("cp.async.cg.shared.global [%0], [%1], 16, %2;"
                 :: "r"(dst), "l"(src), "r"(sz));
}
__device__ __forceinline__ float sigm(float x) { return 1.f / (1.f + expf(-x)); }
__device__ __forceinline__ int ld_acq(const int* p) {
    int v; asm volatile("ld.acquire.gpu.global.s32 %0, [%1];" : "=r"(v) : "l"(p)); return v;
}
__device__ __forceinline__ void st_rel(int* p, int v) {
    asm volatile("st.release.gpu.global.s32 [%0], %1;" :: "l"(p), "r"(v) : "memory");
}

__global__ void init_state() {
    int i = blockIdx.x * blockDim.x + threadIdx.x;
    if (i < 2 * NH * NB) g_ht[i] = 0.f;
    if (i < NBLK * 32)   g_bar[i] = 0;
}

// ---------------- persistent LSTM recurrence ---------------------------------
// Round-11 proven structure (990 us). Changes this round:
//  (a) poll without nanosleep (R4-proven)
//  (b) early flag publish: bar.sync 1,64 inside finalize, then tid0 st.release
//  (c) W_proj bf16 hi/lo split folded into per-step slack (wsplit kernel gone):
//      each (block, step) converts 2-3 vocab columns; loads issue at step top,
//      stores land after the psum barrier.
__global__ void __launch_bounds__(256, 1) lstm_persist(
    const int* __restrict__ enc_in, const int* __restrict__ dec_in,
    const float* __restrict__ E,
    const float* __restrict__ W_enc, const float* __restrict__ b_enc,
    const float* __restrict__ W_dec, const float* __restrict__ b_dec,
    const int* __restrict__ len, const float* __restrict__ Wp)
{
    __shared__ __align__(16) float2 wpen[128][8];
    __shared__ __align__(16) float2 wpdc[128][8];
    __shared__ __align__(16) float2 wxen[64][8];
    __shared__ __align__(16) float2 wxdc[64][8];
    __shared__ float psum[8 * 256];

    int tid  = threadIdx.x;
    int bk   = blockIdx.x;
    int lane = tid & 31;
    int w    = tid >> 5;
    int u0   = bk * 2;

    for (int i = tid; i < 2048; i += 256) {
        int k = i >> 3, c = i & 7;
        int gcol = (c >> 1) * NH + u0 + (c & 1);
        float ve = W_enc[(long)(ND + k) * NG4 + gcol];
        float vd = W_dec[(long)(ND + k) * NG4 + gcol];
        if (k & 1) { wpen[k >> 1][c].y = ve; wpdc[k >> 1][c].y = vd; }
        else       { wpen[k >> 1][c].x = ve; wpdc[k >> 1][c].x = vd; }
    }
    for (int i = tid; i < 1024; i += 256) {
        int k = i >> 3, c = i & 7;
        int gcol = (c >> 1) * NH + u0 + (c & 1);
        float ve = W_enc[(long)k * NG4 + gcol];
        float vd = W_dec[(long)k * NG4 + gcol];
        if (k & 1) { wxen[k >> 1][c].y = ve; wxdc[k >> 1][c].y = vd; }
        else       { wxen[k >> 1][c].x = ve; wxdc[k >> 1][c].x = vd; }
    }

    float creg = 0.f, hreg = 0.f;
    int ul = tid >> 5;
    int bb = tid & 31;
    int mylen = 0;
    float be_i = 0.f, be_j = 0.f, be_f = 0.f, be_o = 0.f;
    float bd_i = 0.f, bd_j = 0.f, bd_f = 0.f, bd_o = 0.f;
    if (tid < 64) {
        mylen = len[bb];
        int u = u0 + ul;
        be_i = b_enc[0 * NH + u]; be_j = b_enc[1 * NH + u];
        be_f = b_enc[2 * NH + u]; be_o = b_enc[3 * NH + u];
        bd_i = b_dec[0 * NH + u]; bd_j = b_dec[1 * NH + u];
        bd_f = b_dec[2 * NH + u]; bd_o = b_dec[3 * NH + u];
    }

    // embedding prefetch for step 0
    float evc[16];
    {
        int tok0 = __ldg(&enc_in[lane * NTX + 0]);
        const float4* er = reinterpret_cast<const float4*>(
            E + (long)tok0 * ND + w * 16);
        float4 e0 = __ldg(er), e1 = __ldg(er + 1);
        float4 e2 = __ldg(er + 2), e3 = __ldg(er + 3);
        evc[0]=e0.x; evc[1]=e0.y; evc[2]=e0.z; evc[3]=e0.w;
        evc[4]=e1.x; evc[5]=e1.y; evc[6]=e1.z; evc[7]=e1.w;
        evc[8]=e2.x; evc[9]=e2.y; evc[10]=e2.z; evc[11]=e2.w;
        evc[12]=e3.x; evc[13]=e3.y; evc[14]=e3.z; evc[15]=e3.w;
    }

    __syncthreads();

    for (int s = 0; s < NSTEPS; s++) {
        int p = s & 1;
        int is_enc = (s < NTX);
        int t = is_enc ? s : s - NTX;

        // ---- (c) W_proj slice loads: thread = k row, 2-3 vocab cols ----
        float wv0, wv1, wv2 = 0.f;
        int widx = s * NBLK + bk;
        int wc0 = widx * 2, wc1 = wc0 + 1;
        int wc2 = (widx < NV - 2 * NSTEPS * NBLK) ? 2 * NSTEPS * NBLK + widx : -1;
        {
            const float* wrowp = Wp + (long)tid * NV;
            wv0 = __ldg(wrowp + wc0);
            wv1 = __ldg(wrowp + wc1);
            if (wc2 >= 0) wv2 = __ldg(wrowp + wc2);
        }

        // ---- issue NEXT step's embedding gather ----
        float evn[16];
        if (s + 1 < NSTEPS) {
            int sn = s + 1;
            int ie = (sn < NTX);
            int tn = ie ? sn : sn - NTX;
            const int* tk = ie ? enc_in : dec_in;
            int Tn = ie ? NTX : NTY;
            int tokn = __ldg(&tk[lane * Tn + tn]);
            const float4* er = reinterpret_cast<const float4*>(
                E + (long)tokn * ND + w * 16);
            float4 e0 = __ldg(er), e1 = __ldg(er + 1);
            float4 e2 = __ldg(er + 2), e3 = __ldg(er + 3);
            evn[0]=e0.x; evn[1]=e0.y; evn[2]=e0.z; evn[3]=e0.w;
            evn[4]=e1.x; evn[5]=e1.y; evn[6]=e1.z; evn[7]=e1.w;
            evn[8]=e2.x; evn[9]=e2.y; evn[10]=e2.z; evn[11]=e2.w;
            evn[12]=e3.x; evn[13]=e3.y; evn[14]=e3.z; evn[15]=e3.w;
        }

        // ---- x-part FMAs from registers ----
        unsigned long long acc2[8];
        #pragma unroll
        for (int c = 0; c < 8; c++) acc2[c] = 0ull;

        const ulonglong2* xrow = is_enc
            ? reinterpret_cast<const ulonglong2*>(&wxen[0][0])
            : reinterpret_cast<const ulonglong2*>(&wxdc[0][0]);
        #pragma unroll
        for (int kp = 0; kp < 8; kp++) {
            unsigned long long a2;
            asm("mov.b64 %0, {%1, %2};" : "=l"(a2)
                : "f"(evc[2 * kp]), "f"(evc[2 * kp + 1]));
            int gkp = w * 8 + kp;
            #pragma unroll
            for (int j = 0; j < 4; j++) {
                ulonglong2 q = xrow[gkp * 4 + j];
                asm("fma.rn.f32x2 %0, %1, %2, %3;"
                    : "=l"(acc2[2 * j]) : "l"(a2), "l"(q.x), "l"(acc2[2 * j]));
                asm("fma.rn.f32x2 %0, %1, %2, %3;"
                    : "=l"(acc2[2 * j + 1]) : "l"(a2), "l"(q.y), "l"(acc2[2 * j + 1]));
            }
        }

        // ---- grid barrier: spread flags, no nanosleep (a) ----
        if (s > 0) {
            if (tid < NBLK) {
                while (ld_acq(&g_bar[tid * 32]) < s) { }
            }
            __syncthreads();
        }

        // ---- h-part ----
        const float* hsrc = g_ht + (long)p * NH * NB;
        float hv[32];
        #pragma unroll
        for (int k = 0; k < 32; k++)
            hv[k] = __ldcg(hsrc + (w * 32 + k) * NB + lane);

        const ulonglong2* wrow = is_enc
            ? reinterpret_cast<const ulonglong2*>(&wpen[0][0])
            : reinterpret_cast<const ulonglong2*>(&wpdc[0][0]);
        #pragma unroll
        for (int kp = 0; kp < 16; kp++) {
            unsigned long long a2;
            asm("mov.b64 %0, {%1, %2};" : "=l"(a2)
                : "f"(hv[2 * kp]), "f"(hv[2 * kp + 1]));
            int gkp = w * 16 + kp;
            #pragma unroll
            for (int j = 0; j < 4; j++) {
                ulonglong2 q = wrow[gkp * 4 + j];
                asm("fma.rn.f32x2 %0, %1, %2, %3;"
                    : "=l"(acc2[2 * j]) : "l"(a2), "l"(q.x), "l"(acc2[2 * j]));
                asm("fma.rn.f32x2 %0, %1, %2, %3;"
                    : "=l"(acc2[2 * j + 1]) : "l"(a2), "l"(q.y), "l"(acc2[2 * j + 1]));
            }
        }
        #pragma unroll
        for (int c = 0; c < 8; c++) {
            float lo = __uint_as_float((unsigned)(acc2[c] & 0xffffffffull));
            float hi = __uint_as_float((unsigned)(acc2[c] >> 32));
            psum[w * 256 + c * 32 + lane] = lo + hi;
        }
        __syncthreads();

        // ---- finalize + early flag publish (b) ----
        if (tid < 64) {
            float zi, zj, zf, zo;
            if (is_enc) { zi = be_i; zj = be_j; zf = be_f; zo = be_o; }
            else        { zi = bd_i; zj = bd_j; zf = bd_f; zo = bd_o; }
            #pragma unroll
            for (int ww = 0; ww < 8; ww++) {
                zi += psum[ww * 256 + (0 + ul) * 32 + bb];
                zj += psum[ww * 256 + (2 + ul) * 32 + bb];
                zf += psum[ww * 256 + (4 + ul) * 32 + bb];
                zo += psum[ww * 256 + (6 + ul) * 32 + bb];
            }
            float nc = creg * sigm(zf + 1.f) + sigm(zi) * tanhf(zj);
            float nh = tanhf(nc) * sigm(zo);
            if (is_enc && t >= mylen) { nc = creg; nh = hreg; }
            creg = nc; hreg = nh;
            int u = u0 + ul;
            g_ht[(long)(p ^ 1) * NH * NB + (long)u * NB + bb] = nh;
            if (!is_enc) {
                __nv_bfloat16 hh = __float2bfloat16(nh);
                float rr = nh - __bfloat162float(hh);
                long mrow = (long)t * NB + bb;
                g_hsh[mrow * NH + u] = hh;
                g_hsl[mrow * NH + u] = __float2bfloat16(rr);
            }
            asm volatile("bar.sync 1, 64;" ::: "memory");
            if (tid == 0) st_rel(&g_bar[bk * 32], s + 1);
        }

        // ---- (c) W_proj slice stores (slack; all 256 threads) ----
        {
            __nv_bfloat16 h0 = __float2bfloat16(wv0);
            g_wth[(long)wc0 * NH + tid] = h0;
            g_wtl[(long)wc0 * NH + tid] =
                __float2bfloat16(wv0 - __bfloat162float(h0));
            __nv_bfloat16 h1 = __float2bfloat16(wv1);
            g_wth[(long)wc1 * NH + tid] = h1;
            g_wtl[(long)wc1 * NH + tid] =
                __float2bfloat16(wv1 - __bfloat162float(h1));
            if (wc2 >= 0) {
                __nv_bfloat16 h2 = __float2bfloat16(wv2);
                g_wth[(long)wc2 * NH + tid] = h2;
                g_wtl[(long)wc2 * NH + tid] =
                    __float2bfloat16(wv2 - __bfloat162float(h2));
            }
        }
        __syncthreads();   // psum WAR protection

        // rotate embedding pipeline
        #pragma unroll
        for (int i = 0; i < 16; i++) evc[i] = evn[i];
    }
}

// ---------------- projection: warp-private B pipeline (round-9 proven) ------
extern __shared__ __align__(16) char proj_sm[];
__global__ void __launch_bounds__(256, 1) proj_mma(float* __restrict__ out)
{
    uint32_t sbase = smem_u32(proj_sm);
    int tid  = threadIdx.x;
    int lane = tid & 31;
    int wid  = tid >> 5;
    int wm   = wid >> 2;
    int wn   = wid & 3;
    int row0 = blockIdx.x * MT;
    int ng   = blockIdx.y;

    for (int i = tid; i < 8192; i += 256) {
        int s = i >> 12, w = i & 4095, row = w >> 5, kseg = w & 31;
        const __nv_bfloat16* src = s ? g_hsl : g_hsh;
        uint4 v = *reinterpret_cast<const uint4*>(
            src + (long)(row0 + row) * NH + kseg * 8);
        *reinterpret_cast<uint4*>(proj_sm + s * ASPLIT + row * APITCH + kseg * 16) = v;
    }
    __syncthreads();

    uint32_t aBase = sbase + (wm * 64 + (lane & 15)) * APITCH + ((lane >> 4) * 8) * 2;
    uint32_t warpB = sbase + B_OFF + wid * BWARP;
    uint32_t bThr  = ((lane & 7) + ((lane >> 4) << 3)) * BROWP
                   + (((lane >> 3) & 1) * 8) * 2;

    for (int nt = ng; nt < NNT; nt += NGP) {
        int col0 = nt * NT;
        int vbase = col0 + wn * 32;

        float acc[4][4][4];
        #pragma unroll
        for (int a = 0; a < 4; a++)
            #pragma unroll
            for (int b = 0; b < 4; b++)
                #pragma unroll
                for (int c = 0; c < 4; c++) acc[a][b][c] = 0.f;

        auto loadB = [&](int c, int buf) {
            #pragma unroll
            for (int q = 0; q < 8; q++) {
                int s = q >> 2;
                int i = lane + 32 * (q & 3);
                int row = i >> 2, seg = i & 3;
                int gv = vbase + row;
                int cgv = gv < NV ? gv : NV - 1;
                const __nv_bfloat16* src =
                    (s ? g_wtl : g_wth) + (long)cgv * NH + c * 32 + seg * 8;
                uint32_t dst = warpB + buf * (2 * BSEG) + s * BSEG
                             + row * BROWP + seg * 16;
                cp16(dst, src, gv < NV ? 16 : 0);
            }
            asm volatile("cp.async.commit_group;" ::: "memory");
        };

        loadB(0, 0);
        loadB(1, 1);

        #pragma unroll 1
        for (int c = 0; c < 8; c++) {
            if (c == 7) { asm volatile("cp.async.wait_group 0;" ::: "memory"); }
            else        { asm volatile("cp.async.wait_group 1;" ::: "memory"); }
            __syncwarp();

            int buf = c & 1;
            uint32_t bufH = warpB + buf * (2 * BSEG) + bThr;
            uint32_t bufL = bufH + BSEG;

            #pragma unroll
            for (int kk = 0; kk < 2; kk++) {
                int kg = c * 32 + kk * 16;
                int kl = kk * 32;
                uint32_t ah[4][4], al[4][4];
                #pragma unroll
                for (int mt = 0; mt < 4; mt++) {
                    ldsm4(ah[mt], aBase + mt * (16 * APITCH) + kg * 2);
                    ldsm4(al[mt], aBase + ASPLIT + mt * (16 * APITCH) + kg * 2);
                }
                uint32_t bh[2][4], bl[2][4];
                #pragma unroll
                for (int l = 0; l < 2; l++) {
                    ldsm4(bh[l], bufH + l * (16 * BROWP) + kl);
                    ldsm4(bl[l], bufL + l * (16 * BROWP) + kl);
                }
                #pragma unroll
                for (int mt = 0; mt < 4; mt++) {
                    #pragma unroll
                    for (int ntl = 0; ntl < 4; ntl++) {
                        int l = ntl >> 1, p = (ntl & 1) * 2;
                        uint32_t bhf[2] = {bh[l][p], bh[l][p + 1]};
                        uint32_t blf[2] = {bl[l][p], bl[l][p + 1]};
                        mma16816(acc[mt][ntl], ah[mt], bhf);
                        mma16816(acc[mt][ntl], ah[mt], blf);
                        mma16816(acc[mt][ntl], al[mt], bhf);
                    }
                }
            }
            if (c + 2 < 8) loadB(c + 2, buf);
        }

        #pragma unroll
        for (int mt = 0; mt < 4; mt++) {
            int r0 = row0 + wm * 64 + mt * 16 + (lane >> 2);
            int r1 = r0 + 8;
            int tt0 = r0 >> 5, bb0 = r0 & 31;
            int tt1 = r1 >> 5, bb1 = r1 & 31;
            float* o0 = out + (long)bb0 * NTY * NV + (long)tt0 * NV;
            float* o1 = out + (long)bb1 * NTY * NV + (long)tt1 * NV;
            #pragma unroll
            for (int ntl = 0; ntl < 4; ntl++) {
                int cc = vbase + ntl * 8 + 2 * (lane & 3);
                if (cc < NV) {
                    float2 v0 = make_float2(acc[mt][ntl][0], acc[mt][ntl][1]);
                    float2 v1 = make_float2(acc[mt][ntl][2], acc[mt][ntl][3]);
                    *reinterpret_cast<float2*>(o0 + cc) = v0;
                    *reinterpret_cast<float2*>(o1 + cc) = v1;
                }
            }
        }
    }
}

// ---------------- launch ----------------------------------------------------
extern "C" void kernel_launch(void* const* d_in, const int* in_sizes, int n_in,
                              void* d_out, int out_size)
{
    const int*   enc_in = (const int*)d_in[0];
    const int*   dec_in = (const int*)d_in[1];
    const int*   len    = (const int*)d_in[2];
    const float* E      = (const float*)d_in[3];
    const float* W_enc  = (const float*)d_in[4];
    const float* b_enc  = (const float*)d_in[5];
    const float* W_dec  = (const float*)d_in[6];
    const float* b_dec  = (const float*)d_in[7];
    const float* W_proj = (const float*)d_in[8];
    float* out = (float*)d_out;

    cudaFuncSetAttribute(proj_mma, cudaFuncAttributeMaxDynamicSharedMemorySize,
                         PROJ_SMEM);

    init_state<<<64, 256>>>();

    lstm_persist<<<NBLK, 256>>>(enc_in, dec_in, E, W_enc, b_enc,
                                W_dec, b_dec, len, W_proj);

    proj_mma<<<dim3(NMT, NGP), 256, PROJ_SMEM>>>(out);
}

// round 14
// speedup vs baseline: 1.2746x; 1.0251x over previous
#include <cuda_runtime.h>
#include <cuda_bf16.h>
#include <math.h>
#include <stdint.h>

// Problem dims
#define NB   32
#define NTX  128
#define NTY  64
#define NV   50000
#define ND   128
#define NH   256
#define NG4  1024
#define NSTEPS (NTX + NTY)
#define NBLK 128

// Projection tiling
#define MT   128
#define NT   128
#define NMT  16
#define NNT  ((NV + NT - 1) / NT)     // 391
#define NGP  9                        // 144 CTAs, single wave

// proj smem layout (bytes from dynamic smem base)
#define APITCH    528
#define ASPLIT    (128 * APITCH)
#define B_OFF     (2 * ASPLIT)
#define BROWP     80
#define BSEG      (32 * BROWP)
#define BWARP     (4 * BSEG)
#define PROJ_SMEM (B_OFF + 8 * BWARP) // 217088

// ---------------- scratch (device globals) ----------------------------------
__device__ float g_ht[2 * NH * NB];
__device__ int   g_bar[NBLK * 32];          // one flag per 128B line (proven)
__device__ __align__(16) __nv_bfloat16 g_hsh[NTY * NB * NH];
__device__ __align__(16) __nv_bfloat16 g_hsl[NTY * NB * NH];
__device__ __align__(16) __nv_bfloat16 g_wth[(long)NV * NH];
__device__ __align__(16) __nv_bfloat16 g_wtl[(long)NV * NH];

// ---------------- helpers ----------------------------------------------------
__device__ __forceinline__ uint32_t smem_u32(const void* p) {
    uint32_t a;
    asm("{ .reg .u64 t; cvta.to.shared.u64 t, %1; cvt.u32.u64 %0, t; }"
        : "=r"(a) : "l"(p));
    return a;
}
__device__ __forceinline__ void ldsm4(uint32_t* r, uint32_t addr) {
    asm volatile("ldmatrix.sync.aligned.m8n8.x4.shared.b16 {%0,%1,%2,%3}, [%4];"
                 : "=r"(r[0]), "=r"(r[1]), "=r"(r[2]), "=r"(r[3]) : "r"(addr));
}
__device__ __forceinline__ void mma16816(float* c, const uint32_t* a,
                                         const uint32_t* b) {
    asm volatile(
        "mma.sync.aligned.m16n8k16.row.col.f32.bf16.bf16.f32 "
        "{%0,%1,%2,%3}, {%4,%5,%6,%7}, {%8,%9}, {%0,%1,%2,%3};"
        : "+f"(c[0]), "+f"(c[1]), "+f"(c[2]), "+f"(c[3])
        : "r"(a[0]), "r"(a[1]), "r"(a[2]), "r"(a[3]), "r"(b[0]), "r"(b[1]));
}
__device__ __forceinline__ void cp16(uint32_t dst, const void* src, int sz) {
    asm volatile("cp.async.cg.shared.global [%0], [%1], 16, %2;"
                 :: "r"(dst), "l"(src), "r"(sz));
}
__device__ __forceinline__ float sigm(float x) { return 1.f / (1.f + expf(-x)); }
__device__ __forceinline__ int ld_acq(const int* p) {
    int v; asm volatile("ld.acquire.gpu.global.s32 %0, [%1];" : "=r"(v) : "l"(p)); return v;
}
__device__ __forceinline__ void st_rel(int* p, int v) {
    asm volatile("st.release.gpu.global.s32 [%0], %1;" :: "l"(p), "r"(v) : "memory");
}

__global__ void init_state() {
    int i = blockIdx.x * blockDim.x + threadIdx.x;
    if (i < 2 * NH * NB) g_ht[i] = 0.f;
    if (i < NBLK * 32)   g_bar[i] = 0;
}

// ---------------- W_proj transpose + bf16 hi/lo split ------------------------
__global__ void __launch_bounds__(256) wsplit(const float* __restrict__ W) {
    __shared__ float tile[32][33];
    int v0 = blockIdx.x * 32, k0 = blockIdx.y * 32;
    int tx = threadIdx.x & 31, ty = threadIdx.x >> 5;
    #pragma unroll
    for (int i = 0; i < 4; i++) {
        int k = k0 + ty + i * 8, v = v0 + tx;
        tile[ty + i * 8][tx] = (v < NV) ? W[(long)k * NV + v] : 0.f;
    }
    __syncthreads();
    #pragma unroll
    for (int i = 0; i < 4; i++) {
        int v = v0 + ty + i * 8;
        if (v < NV) {
            float x = tile[tx][ty + i * 8];
            __nv_bfloat16 h = __float2bfloat16(x);
            float r = x - __bfloat162float(h);
            g_wth[(long)v * NH + k0 + tx] = h;
            g_wtl[(long)v * NH + k0 + tx] = __float2bfloat16(r);
        }
    }
}

// ---------------- persistent LSTM recurrence ---------------------------------
// Round-11 structure (990 us) with exactly two sync edits:
//  (a) flag poll without nanosleep
//  (b) early flag publish: finalize warps join bar.sync 1,64, tid0 st.release
//      BEFORE the trailing __syncthreads (which only protects psum WAR).
__global__ void __launch_bounds__(256, 1) lstm_persist(
    const int* __restrict__ enc_in, const int* __restrict__ dec_in,
    const float* __restrict__ E,
    const float* __restrict__ W_enc, const float* __restrict__ b_enc,
    const float* __restrict__ W_dec, const float* __restrict__ b_dec,
    const int* __restrict__ len)
{
    __shared__ __align__(16) float2 wpen[128][8];
    __shared__ __align__(16) float2 wpdc[128][8];
    __shared__ __align__(16) float2 wxen[64][8];
    __shared__ __align__(16) float2 wxdc[64][8];
    __shared__ float psum[8 * 256];

    int tid  = threadIdx.x;
    int bk   = blockIdx.x;
    int lane = tid & 31;
    int w    = tid >> 5;
    int u0   = bk * 2;

    for (int i = tid; i < 2048; i += 256) {
        int k = i >> 3, c = i & 7;
        int gcol = (c >> 1) * NH + u0 + (c & 1);
        float ve = W_enc[(long)(ND + k) * NG4 + gcol];
        float vd = W_dec[(long)(ND + k) * NG4 + gcol];
        if (k & 1) { wpen[k >> 1][c].y = ve; wpdc[k >> 1][c].y = vd; }
        else       { wpen[k >> 1][c].x = ve; wpdc[k >> 1][c].x = vd; }
    }
    for (int i = tid; i < 1024; i += 256) {
        int k = i >> 3, c = i & 7;
        int gcol = (c >> 1) * NH + u0 + (c & 1);
        float ve = W_enc[(long)k * NG4 + gcol];
        float vd = W_dec[(long)k * NG4 + gcol];
        if (k & 1) { wxen[k >> 1][c].y = ve; wxdc[k >> 1][c].y = vd; }
        else       { wxen[k >> 1][c].x = ve; wxdc[k >> 1][c].x = vd; }
    }

    float creg = 0.f, hreg = 0.f;
    int ul = tid >> 5;
    int bb = tid & 31;
    int mylen = 0;
    float be_i = 0.f, be_j = 0.f, be_f = 0.f, be_o = 0.f;
    float bd_i = 0.f, bd_j = 0.f, bd_f = 0.f, bd_o = 0.f;
    if (tid < 64) {
        mylen = len[bb];
        int u = u0 + ul;
        be_i = b_enc[0 * NH + u]; be_j = b_enc[1 * NH + u];
        be_f = b_enc[2 * NH + u]; be_o = b_enc[3 * NH + u];
        bd_i = b_dec[0 * NH + u]; bd_j = b_dec[1 * NH + u];
        bd_f = b_dec[2 * NH + u]; bd_o = b_dec[3 * NH + u];
    }

    // embedding prefetch for step 0
    float evc[16];
    {
        int tok0 = __ldg(&enc_in[lane * NTX + 0]);
        const float4* er = reinterpret_cast<const float4*>(
            E + (long)tok0 * ND + w * 16);
        float4 e0 = __ldg(er), e1 = __ldg(er + 1);
        float4 e2 = __ldg(er + 2), e3 = __ldg(er + 3);
        evc[0]=e0.x; evc[1]=e0.y; evc[2]=e0.z; evc[3]=e0.w;
        evc[4]=e1.x; evc[5]=e1.y; evc[6]=e1.z; evc[7]=e1.w;
        evc[8]=e2.x; evc[9]=e2.y; evc[10]=e2.z; evc[11]=e2.w;
        evc[12]=e3.x; evc[13]=e3.y; evc[14]=e3.z; evc[15]=e3.w;
    }

    __syncthreads();

    for (int s = 0; s < NSTEPS; s++) {
        int p = s & 1;
        int is_enc = (s < NTX);
        int t = is_enc ? s : s - NTX;

        // ---- issue NEXT step's embedding gather ----
        float evn[16];
        if (s + 1 < NSTEPS) {
            int sn = s + 1;
            int ie = (sn < NTX);
            int tn = ie ? sn : sn - NTX;
            const int* tk = ie ? enc_in : dec_in;
            int Tn = ie ? NTX : NTY;
            int tokn = __ldg(&tk[lane * Tn + tn]);
            const float4* er = reinterpret_cast<const float4*>(
                E + (long)tokn * ND + w * 16);
            float4 e0 = __ldg(er), e1 = __ldg(er + 1);
            float4 e2 = __ldg(er + 2), e3 = __ldg(er + 3);
            evn[0]=e0.x; evn[1]=e0.y; evn[2]=e0.z; evn[3]=e0.w;
            evn[4]=e1.x; evn[5]=e1.y; evn[6]=e1.z; evn[7]=e1.w;
            evn[8]=e2.x; evn[9]=e2.y; evn[10]=e2.z; evn[11]=e2.w;
            evn[12]=e3.x; evn[13]=e3.y; evn[14]=e3.z; evn[15]=e3.w;
        }

        // ---- x-part FMAs from registers ----
        unsigned long long acc2[8];
        #pragma unroll
        for (int c = 0; c < 8; c++) acc2[c] = 0ull;

        const ulonglong2* xrow = is_enc
            ? reinterpret_cast<const ulonglong2*>(&wxen[0][0])
            : reinterpret_cast<const ulonglong2*>(&wxdc[0][0]);
        #pragma unroll
        for (int kp = 0; kp < 8; kp++) {
            unsigned long long a2;
            asm("mov.b64 %0, {%1, %2};" : "=l"(a2)
                : "f"(evc[2 * kp]), "f"(evc[2 * kp + 1]));
            int gkp = w * 8 + kp;
            #pragma unroll
            for (int j = 0; j < 4; j++) {
                ulonglong2 q = xrow[gkp * 4 + j];
                asm("fma.rn.f32x2 %0, %1, %2, %3;"
                    : "=l"(acc2[2 * j]) : "l"(a2), "l"(q.x), "l"(acc2[2 * j]));
                asm("fma.rn.f32x2 %0, %1, %2, %3;"
                    : "=l"(acc2[2 * j + 1]) : "l"(a2), "l"(q.y), "l"(acc2[2 * j + 1]));
            }
        }

        // ---- grid barrier: spread flags, no nanosleep (a) ----
        if (s > 0) {
            if (tid < NBLK) {
                while (ld_acq(&g_bar[tid * 32]) < s) { }
            }
            __syncthreads();
        }

        // ---- h-part ----
        const float* hsrc = g_ht + (long)p * NH * NB;
        float hv[32];
        #pragma unroll
        for (int k = 0; k < 32; k++)
            hv[k] = __ldcg(hsrc + (w * 32 + k) * NB + lane);

        const ulonglong2* wrow = is_enc
            ? reinterpret_cast<const ulonglong2*>(&wpen[0][0])
            : reinterpret_cast<const ulonglong2*>(&wpdc[0][0]);
        #pragma unroll
        for (int kp = 0; kp < 16; kp++) {
            unsigned long long a2;
            asm("mov.b64 %0, {%1, %2};" : "=l"(a2)
                : "f"(hv[2 * kp]), "f"(hv[2 * kp + 1]));
            int gkp = w * 16 + kp;
            #pragma unroll
            for (int j = 0; j < 4; j++) {
                ulonglong2 q = wrow[gkp * 4 + j];
                asm("fma.rn.f32x2 %0, %1, %2, %3;"
                    : "=l"(acc2[2 * j]) : "l"(a2), "l"(q.x), "l"(acc2[2 * j]));
                asm("fma.rn.f32x2 %0, %1, %2, %3;"
                    : "=l"(acc2[2 * j + 1]) : "l"(a2), "l"(q.y), "l"(acc2[2 * j + 1]));
            }
        }
        #pragma unroll
        for (int c = 0; c < 8; c++) {
            float lo = __uint_as_float((unsigned)(acc2[c] & 0xffffffffull));
            float hi = __uint_as_float((unsigned)(acc2[c] >> 32));
            psum[w * 256 + c * 32 + lane] = lo + hi;
        }
        __syncthreads();

        // ---- finalize + early flag publish (b) ----
        if (tid < 64) {
            float zi, zj, zf, zo;
            if (is_enc) { zi = be_i; zj = be_j; zf = be_f; zo = be_o; }
            else        { zi = bd_i; zj = bd_j; zf = bd_f; zo = bd_o; }
            #pragma unroll
            for (int ww = 0; ww < 8; ww++) {
                zi += psum[ww * 256 + (0 + ul) * 32 + bb];
                zj += psum[ww * 256 + (2 + ul) * 32 + bb];
                zf += psum[ww * 256 + (4 + ul) * 32 + bb];
                zo += psum[ww * 256 + (6 + ul) * 32 + bb];
            }
            float nc = creg * sigm(zf + 1.f) + sigm(zi) * tanhf(zj);
            float nh = tanhf(nc) * sigm(zo);
            if (is_enc && t >= mylen) { nc = creg; nh = hreg; }
            creg = nc; hreg = nh;
            int u = u0 + ul;
            g_ht[(long)(p ^ 1) * NH * NB + (long)u * NB + bb] = nh;
            if (!is_enc) {
                __nv_bfloat16 hh = __float2bfloat16(nh);
                float rr = nh - __bfloat162float(hh);
                long mrow = (long)t * NB + bb;
                g_hsh[mrow * NH + u] = hh;
                g_hsl[mrow * NH + u] = __float2bfloat16(rr);
            }
            asm volatile("bar.sync 1, 64;" ::: "memory");
            if (tid == 0) st_rel(&g_bar[bk * 32], s + 1);
        }
        __syncthreads();   // psum WAR protection

        // rotate embedding pipeline
        #pragma unroll
        for (int i = 0; i < 16; i++) evc[i] = evn[i];
    }
}

// ---------------- projection: warp-private B pipeline (round-9 proven) ------
extern __shared__ __align__(16) char proj_sm[];
__global__ void __launch_bounds__(256, 1) proj_mma(float* __restrict__ out)
{
    uint32_t sbase = smem_u32(proj_sm);
    int tid  = threadIdx.x;
    int lane = tid & 31;
    int wid  = tid >> 5;
    int wm   = wid >> 2;
    int wn   = wid & 3;
    int row0 = blockIdx.x * MT;
    int ng   = blockIdx.y;

    for (int i = tid; i < 8192; i += 256) {
        int s = i >> 12, w = i & 4095, row = w >> 5, kseg = w & 31;
        const __nv_bfloat16* src = s ? g_hsl : g_hsh;
        uint4 v = *reinterpret_cast<const uint4*>(
            src + (long)(row0 + row) * NH + kseg * 8);
        *reinterpret_cast<uint4*>(proj_sm + s * ASPLIT + row * APITCH + kseg * 16) = v;
    }
    __syncthreads();

    uint32_t aBase = sbase + (wm * 64 + (lane & 15)) * APITCH + ((lane >> 4) * 8) * 2;
    uint32_t warpB = sbase + B_OFF + wid * BWARP;
    uint32_t bThr  = ((lane & 7) + ((lane >> 4) << 3)) * BROWP
                   + (((lane >> 3) & 1) * 8) * 2;

    for (int nt = ng; nt < NNT; nt += NGP) {
        int col0 = nt * NT;
        int vbase = col0 + wn * 32;

        float acc[4][4][4];
        #pragma unroll
        for (int a = 0; a < 4; a++)
            #pragma unroll
            for (int b = 0; b < 4; b++)
                #pragma unroll
                for (int c = 0; c < 4; c++) acc[a][b][c] = 0.f;

        auto loadB = [&](int c, int buf) {
            #pragma unroll
            for (int q = 0; q < 8; q++) {
                int s = q >> 2;
                int i = lane + 32 * (q & 3);
                int row = i >> 2, seg = i & 3;
                int gv = vbase + row;
                int cgv = gv < NV ? gv : NV - 1;
                const __nv_bfloat16* src =
                    (s ? g_wtl : g_wth) + (long)cgv * NH + c * 32 + seg * 8;
                uint32_t dst = warpB + buf * (2 * BSEG) + s * BSEG
                             + row * BROWP + seg * 16;
                cp16(dst, src, gv < NV ? 16 : 0);
            }
            asm volatile("cp.async.commit_group;" ::: "memory");
        };

        loadB(0, 0);
        loadB(1, 1);

        #pragma unroll 1
        for (int c = 0; c < 8; c++) {
            if (c == 7) { asm volatile("cp.async.wait_group 0;" ::: "memory"); }
            else        { asm volatile("cp.async.wait_group 1;" ::: "memory"); }
            __syncwarp();

            int buf = c & 1;
            uint32_t bufH = warpB + buf * (2 * BSEG) + bThr;
            uint32_t bufL = bufH + BSEG;

            #pragma unroll
            for (int kk = 0; kk < 2; kk++) {
                int kg = c * 32 + kk * 16;
                int kl = kk * 32;
                uint32_t ah[4][4], al[4][4];
                #pragma unroll
                for (int mt = 0; mt < 4; mt++) {
                    ldsm4(ah[mt], aBase + mt * (16 * APITCH) + kg * 2);
                    ldsm4(al[mt], aBase + ASPLIT + mt * (16 * APITCH) + kg * 2);
                }
                uint32_t bh[2][4], bl[2][4];
                #pragma unroll
                for (int l = 0; l < 2; l++) {
                    ldsm4(bh[l], bufH + l * (16 * BROWP) + kl);
                    ldsm4(bl[l], bufL + l * (16 * BROWP) + kl);
                }
                #pragma unroll
                for (int mt = 0; mt < 4; mt++) {
                    #pragma unroll
                    for (int ntl = 0; ntl < 4; ntl++) {
                        int l = ntl >> 1, p = (ntl & 1) * 2;
                        uint32_t bhf[2] = {bh[l][p], bh[l][p + 1]};
                        uint32_t blf[2] = {bl[l][p], bl[l][p + 1]};
                        mma16816(acc[mt][ntl], ah[mt], bhf);
                        mma16816(acc[mt][ntl], ah[mt], blf);
                        mma16816(acc[mt][ntl], al[mt], bhf);
                    }
                }
            }
            if (c + 2 < 8) loadB(c + 2, buf);
        }

        #pragma unroll
        for (int mt = 0; mt < 4; mt++) {
            int r0 = row0 + wm * 64 + mt * 16 + (lane >> 2);
            int r1 = r0 + 8;
            int tt0 = r0 >> 5, bb0 = r0 & 31;
            int tt1 = r1 >> 5, bb1 = r1 & 31;
            float* o0 = out + (long)bb0 * NTY * NV + (long)tt0 * NV;
            float* o1 = out + (long)bb1 * NTY * NV + (long)tt1 * NV;
            #pragma unroll
            for (int ntl = 0; ntl < 4; ntl++) {
                int cc = vbase + ntl * 8 + 2 * (lane & 3);
                if (cc < NV) {
                    float2 v0 = make_float2(acc[mt][ntl][0], acc[mt][ntl][1]);
                    float2 v1 = make_float2(acc[mt][ntl][2], acc[mt][ntl][3]);
                    *reinterpret_cast<float2*>(o0 + cc) = v0;
                    *reinterpret_cast<float2*>(o1 + cc) = v1;
                }
            }
        }
    }
}

// ---------------- launch ----------------------------------------------------
extern "C" void kernel_launch(void* const* d_in, const int* in_sizes, int n_in,
                              void* d_out, int out_size)
{
    const int*   enc_in = (const int*)d_in[0];
    const int*   dec_in = (const int*)d_in[1];
    const int*   len    = (const int*)d_in[2];
    const float* E      = (const float*)d_in[3];
    const float* W_enc  = (const float*)d_in[4];
    const float* b_enc  = (const float*)d_in[5];
    const float* W_dec  = (const float*)d_in[6];
    const float* b_dec  = (const float*)d_in[7];
    const float* W_proj = (const float*)d_in[8];
    float* out = (float*)d_out;

    cudaFuncSetAttribute(proj_mma, cudaFuncAttributeMaxDynamicSharedMemorySize,
                         PROJ_SMEM);

    init_state<<<64, 256>>>();

    wsplit<<<dim3((NV + 31) / 32, 8), 256>>>(W_proj);

    lstm_persist<<<NBLK, 256>>>(enc_in, dec_in, E, W_enc, b_enc,
                                W_dec, b_dec, len);

    proj_mma<<<dim3(NMT, NGP), 256, PROJ_SMEM>>>(out);
}

// round 15
// speedup vs baseline: 1.3173x; 1.0335x over previous
#include <cuda_runtime.h>
#include <cuda_bf16.h>
#include <math.h>
#include <stdint.h>

// Problem dims
#define NB   32
#define NTX  128
#define NTY  64
#define NV   50000
#define ND   128
#define NH   256
#define NG4  1024
#define NSTEPS (NTX + NTY)
#define NBLK 128

// Projection tiling
#define MT   128
#define NT   128
#define NMT  16
#define NNT  ((NV + NT - 1) / NT)     // 391
#define NGP  9                        // 144 CTAs, single wave

// proj smem layout (bytes from dynamic smem base)
#define APITCH    528
#define ASPLIT    (128 * APITCH)
#define B_OFF     (2 * ASPLIT)
#define BROWP     80
#define BSEG      (32 * BROWP)
#define BWARP     (4 * BSEG)
#define PROJ_SMEM (B_OFF + 8 * BWARP) // 217088

// ---------------- scratch (device globals) ----------------------------------
__device__ float g_ht[2 * NH * NB];
__device__ int   g_bar[NBLK * 32];          // one flag per 128B line (proven)
__device__ __align__(16) __nv_bfloat16 g_hsh[NTY * NB * NH];
__device__ __align__(16) __nv_bfloat16 g_hsl[NTY * NB * NH];
__device__ __align__(16) __nv_bfloat16 g_wth[(long)NV * NH];
__device__ __align__(16) __nv_bfloat16 g_wtl[(long)NV * NH];

// ---------------- helpers ----------------------------------------------------
__device__ __forceinline__ uint32_t smem_u32(const void* p) {
    uint32_t a;
    asm("{ .reg .u64 t; cvta.to.shared.u64 t, %1; cvt.u32.u64 %0, t; }"
        : "=r"(a) : "l"(p));
    return a;
}
__device__ __forceinline__ void ldsm4(uint32_t* r, uint32_t addr) {
    asm volatile("ldmatrix.sync.aligned.m8n8.x4.shared.b16 {%0,%1,%2,%3}, [%4];"
                 : "=r"(r[0]), "=r"(r[1]), "=r"(r[2]), "=r"(r[3]) : "r"(addr));
}
__device__ __forceinline__ void mma16816(float* c, const uint32_t* a,
                                         const uint32_t* b) {
    asm volatile(
        "mma.sync.aligned.m16n8k16.row.col.f32.bf16.bf16.f32 "
        "{%0,%1,%2,%3}, {%4,%5,%6,%7}, {%8,%9}, {%0,%1,%2,%3};"
        : "+f"(c[0]), "+f"(c[1]), "+f"(c[2]), "+f"(c[3])
        : "r"(a[0]), "r"(a[1]), "r"(a[2]), "r"(a[3]), "r"(b[0]), "r"(b[1]));
}
__device__ __forceinline__ void cp16(uint32_t dst, const void* src, int sz) {
    asm volatile("cp.async.cg.shared.global [%0], [%1], 16, %2;"
                 :: "r"(dst), "l"(src), "r"(sz));
}
__device__ __forceinline__ float sigm(float x) { return 1.f / (1.f + expf(-x)); }
__device__ __forceinline__ int ld_acq(const int* p) {
    int v; asm volatile("ld.acquire.gpu.global.s32 %0, [%1];" : "=r"(v) : "l"(p)); return v;
}
__device__ __forceinline__ void st_rel(int* p, int v) {
    asm volatile("st.release.gpu.global.s32 [%0], %1;" :: "l"(p), "r"(v) : "memory");
}

__global__ void init_state() {
    int i = blockIdx.x * blockDim.x + threadIdx.x;
    if (i < 2 * NH * NB) g_ht[i] = 0.f;
    if (i < NBLK * 32)   g_bar[i] = 0;
}

// ---------------- W_proj transpose + bf16 hi/lo split ------------------------
__global__ void __launch_bounds__(256) wsplit(const float* __restrict__ W) {
    __shared__ float tile[32][33];
    int v0 = blockIdx.x * 32, k0 = blockIdx.y * 32;
    int tx = threadIdx.x & 31, ty = threadIdx.x >> 5;
    #pragma unroll
    for (int i = 0; i < 4; i++) {
        int k = k0 + ty + i * 8, v = v0 + tx;
        tile[ty + i * 8][tx] = (v < NV) ? W[(long)k * NV + v] : 0.f;
    }
    __syncthreads();
    #pragma unroll
    for (int i = 0; i < 4; i++) {
        int v = v0 + ty + i * 8;
        if (v < NV) {
            float x = tile[tx][ty + i * 8];
            __nv_bfloat16 h = __float2bfloat16(x);
            float r = x - __bfloat162float(h);
            g_wth[(long)v * NH + k0 + tx] = h;
            g_wtl[(long)v * NH + k0 + tx] = __float2bfloat16(r);
        }
    }
}

// ---------------- persistent LSTM recurrence (round-11 proven, frozen) ------
__global__ void __launch_bounds__(256, 1) lstm_persist(
    const int* __restrict__ enc_in, const int* __restrict__ dec_in,
    const float* __restrict__ E,
    const float* __restrict__ W_enc, const float* __restrict__ b_enc,
    const float* __restrict__ W_dec, const float* __restrict__ b_dec,
    const int* __restrict__ len)
{
    __shared__ __align__(16) float2 wpen[128][8];
    __shared__ __align__(16) float2 wpdc[128][8];
    __shared__ __align__(16) float2 wxen[64][8];
    __shared__ __align__(16) float2 wxdc[64][8];
    __shared__ float psum[8 * 256];

    int tid  = threadIdx.x;
    int bk   = blockIdx.x;
    int lane = tid & 31;
    int w    = tid >> 5;
    int u0   = bk * 2;

    for (int i = tid; i < 2048; i += 256) {
        int k = i >> 3, c = i & 7;
        int gcol = (c >> 1) * NH + u0 + (c & 1);
        float ve = W_enc[(long)(ND + k) * NG4 + gcol];
        float vd = W_dec[(long)(ND + k) * NG4 + gcol];
        if (k & 1) { wpen[k >> 1][c].y = ve; wpdc[k >> 1][c].y = vd; }
        else       { wpen[k >> 1][c].x = ve; wpdc[k >> 1][c].x = vd; }
    }
    for (int i = tid; i < 1024; i += 256) {
        int k = i >> 3, c = i & 7;
        int gcol = (c >> 1) * NH + u0 + (c & 1);
        float ve = W_enc[(long)k * NG4 + gcol];
        float vd = W_dec[(long)k * NG4 + gcol];
        if (k & 1) { wxen[k >> 1][c].y = ve; wxdc[k >> 1][c].y = vd; }
        else       { wxen[k >> 1][c].x = ve; wxdc[k >> 1][c].x = vd; }
    }

    float creg = 0.f, hreg = 0.f;
    int ul = tid >> 5;
    int bb = tid & 31;
    int mylen = 0;
    float be_i = 0.f, be_j = 0.f, be_f = 0.f, be_o = 0.f;
    float bd_i = 0.f, bd_j = 0.f, bd_f = 0.f, bd_o = 0.f;
    if (tid < 64) {
        mylen = len[bb];
        int u = u0 + ul;
        be_i = b_enc[0 * NH + u]; be_j = b_enc[1 * NH + u];
        be_f = b_enc[2 * NH + u]; be_o = b_enc[3 * NH + u];
        bd_i = b_dec[0 * NH + u]; bd_j = b_dec[1 * NH + u];
        bd_f = b_dec[2 * NH + u]; bd_o = b_dec[3 * NH + u];
    }

    // embedding prefetch for step 0
    float evc[16];
    {
        int tok0 = __ldg(&enc_in[lane * NTX + 0]);
        const float4* er = reinterpret_cast<const float4*>(
            E + (long)tok0 * ND + w * 16);
        float4 e0 = __ldg(er), e1 = __ldg(er + 1);
        float4 e2 = __ldg(er + 2), e3 = __ldg(er + 3);
        evc[0]=e0.x; evc[1]=e0.y; evc[2]=e0.z; evc[3]=e0.w;
        evc[4]=e1.x; evc[5]=e1.y; evc[6]=e1.z; evc[7]=e1.w;
        evc[8]=e2.x; evc[9]=e2.y; evc[10]=e2.z; evc[11]=e2.w;
        evc[12]=e3.x; evc[13]=e3.y; evc[14]=e3.z; evc[15]=e3.w;
    }

    __syncthreads();

    for (int s = 0; s < NSTEPS; s++) {
        int p = s & 1;
        int is_enc = (s < NTX);
        int t = is_enc ? s : s - NTX;

        // ---- issue NEXT step's embedding gather ----
        float evn[16];
        if (s + 1 < NSTEPS) {
            int sn = s + 1;
            int ie = (sn < NTX);
            int tn = ie ? sn : sn - NTX;
            const int* tk = ie ? enc_in : dec_in;
            int Tn = ie ? NTX : NTY;
            int tokn = __ldg(&tk[lane * Tn + tn]);
            const float4* er = reinterpret_cast<const float4*>(
                E + (long)tokn * ND + w * 16);
            float4 e0 = __ldg(er), e1 = __ldg(er + 1);
            float4 e2 = __ldg(er + 2), e3 = __ldg(er + 3);
            evn[0]=e0.x; evn[1]=e0.y; evn[2]=e0.z; evn[3]=e0.w;
            evn[4]=e1.x; evn[5]=e1.y; evn[6]=e1.z; evn[7]=e1.w;
            evn[8]=e2.x; evn[9]=e2.y; evn[10]=e2.z; evn[11]=e2.w;
            evn[12]=e3.x; evn[13]=e3.y; evn[14]=e3.z; evn[15]=e3.w;
        }

        // ---- x-part FMAs from registers ----
        unsigned long long acc2[8];
        #pragma unroll
        for (int c = 0; c < 8; c++) acc2[c] = 0ull;

        const ulonglong2* xrow = is_enc
            ? reinterpret_cast<const ulonglong2*>(&wxen[0][0])
            : reinterpret_cast<const ulonglong2*>(&wxdc[0][0]);
        #pragma unroll
        for (int kp = 0; kp < 8; kp++) {
            unsigned long long a2;
            asm("mov.b64 %0, {%1, %2};" : "=l"(a2)
                : "f"(evc[2 * kp]), "f"(evc[2 * kp + 1]));
            int gkp = w * 8 + kp;
            #pragma unroll
            for (int j = 0; j < 4; j++) {
                ulonglong2 q = xrow[gkp * 4 + j];
                asm("fma.rn.f32x2 %0, %1, %2, %3;"
                    : "=l"(acc2[2 * j]) : "l"(a2), "l"(q.x), "l"(acc2[2 * j]));
                asm("fma.rn.f32x2 %0, %1, %2, %3;"
                    : "=l"(acc2[2 * j + 1]) : "l"(a2), "l"(q.y), "l"(acc2[2 * j + 1]));
            }
        }

        // ---- grid barrier (R11 proven: nanosleep poll) ----
        if (s > 0) {
            if (tid < NBLK) {
                while (ld_acq(&g_bar[tid * 32]) < s) { __nanosleep(32); }
            }
            __syncthreads();
        }

        // ---- h-part ----
        const float* hsrc = g_ht + (long)p * NH * NB;
        float hv[32];
        #pragma unroll
        for (int k = 0; k < 32; k++)
            hv[k] = __ldcg(hsrc + (w * 32 + k) * NB + lane);

        const ulonglong2* wrow = is_enc
            ? reinterpret_cast<const ulonglong2*>(&wpen[0][0])
            : reinterpret_cast<const ulonglong2*>(&wpdc[0][0]);
        #pragma unroll
        for (int kp = 0; kp < 16; kp++) {
            unsigned long long a2;
            asm("mov.b64 %0, {%1, %2};" : "=l"(a2)
                : "f"(hv[2 * kp]), "f"(hv[2 * kp + 1]));
            int gkp = w * 16 + kp;
            #pragma unroll
            for (int j = 0; j < 4; j++) {
                ulonglong2 q = wrow[gkp * 4 + j];
                asm("fma.rn.f32x2 %0, %1, %2, %3;"
                    : "=l"(acc2[2 * j]) : "l"(a2), "l"(q.x), "l"(acc2[2 * j]));
                asm("fma.rn.f32x2 %0, %1, %2, %3;"
                    : "=l"(acc2[2 * j + 1]) : "l"(a2), "l"(q.y), "l"(acc2[2 * j + 1]));
            }
        }
        #pragma unroll
        for (int c = 0; c < 8; c++) {
            float lo = __uint_as_float((unsigned)(acc2[c] & 0xffffffffull));
            float hi = __uint_as_float((unsigned)(acc2[c] >> 32));
            psum[w * 256 + c * 32 + lane] = lo + hi;
        }
        __syncthreads();

        // ---- finalize ----
        if (tid < 64) {
            float zi, zj, zf, zo;
            if (is_enc) { zi = be_i; zj = be_j; zf = be_f; zo = be_o; }
            else        { zi = bd_i; zj = bd_j; zf = bd_f; zo = bd_o; }
            #pragma unroll
            for (int ww = 0; ww < 8; ww++) {
                zi += psum[ww * 256 + (0 + ul) * 32 + bb];
                zj += psum[ww * 256 + (2 + ul) * 32 + bb];
                zf += psum[ww * 256 + (4 + ul) * 32 + bb];
                zo += psum[ww * 256 + (6 + ul) * 32 + bb];
            }
            float nc = creg * sigm(zf + 1.f) + sigm(zi) * tanhf(zj);
            float nh = tanhf(nc) * sigm(zo);
            if (is_enc && t >= mylen) { nc = creg; nh = hreg; }
            creg = nc; hreg = nh;
            int u = u0 + ul;
            g_ht[(long)(p ^ 1) * NH * NB + (long)u * NB + bb] = nh;
            if (!is_enc) {
                __nv_bfloat16 hh = __float2bfloat16(nh);
                float rr = nh - __bfloat162float(hh);
                long mrow = (long)t * NB + bb;
                g_hsh[mrow * NH + u] = hh;
                g_hsl[mrow * NH + u] = __float2bfloat16(rr);
            }
        }
        __syncthreads();
        if (tid == 0) st_rel(&g_bar[bk * 32], s + 1);

        // rotate embedding pipeline
        #pragma unroll
        for (int i = 0; i < 16; i++) evc[i] = evn[i];
    }
}

// ---------------- projection: warp-private B + cross-tile pipeline ----------
// NEW: next N-tile's chunk-0/1 cp.asyncs issue as bufs free (during chunks
// 6/7), so loads complete under the epilogue and the next tile starts hot.
extern __shared__ __align__(16) char proj_sm[];
__global__ void __launch_bounds__(256, 1) proj_mma(float* __restrict__ out)
{
    uint32_t sbase = smem_u32(proj_sm);
    int tid  = threadIdx.x;
    int lane = tid & 31;
    int wid  = tid >> 5;
    int wm   = wid >> 2;
    int wn   = wid & 3;
    int row0 = blockIdx.x * MT;
    int ng   = blockIdx.y;

    for (int i = tid; i < 8192; i += 256) {
        int s = i >> 12, w = i & 4095, row = w >> 5, kseg = w & 31;
        const __nv_bfloat16* src = s ? g_hsl : g_hsh;
        uint4 v = *reinterpret_cast<const uint4*>(
            src + (long)(row0 + row) * NH + kseg * 8);
        *reinterpret_cast<uint4*>(proj_sm + s * ASPLIT + row * APITCH + kseg * 16) = v;
    }
    __syncthreads();

    uint32_t aBase = sbase + (wm * 64 + (lane & 15)) * APITCH + ((lane >> 4) * 8) * 2;
    uint32_t warpB = sbase + B_OFF + wid * BWARP;
    uint32_t bThr  = ((lane & 7) + ((lane >> 4) << 3)) * BROWP
                   + (((lane >> 3) & 1) * 8) * 2;

    // per-warp B chunk loader (vb = vocab base of this warp's 32 rows)
    auto loadB = [&](int vb, int c, int buf) {
        #pragma unroll
        for (int q = 0; q < 8; q++) {
            int s = q >> 2;
            int i = lane + 32 * (q & 3);
            int row = i >> 2, seg = i & 3;
            int gv = vb + row;
            int cgv = gv < NV ? gv : NV - 1;
            const __nv_bfloat16* src =
                (s ? g_wtl : g_wth) + (long)cgv * NH + c * 32 + seg * 8;
            uint32_t dst = warpB + buf * (2 * BSEG) + s * BSEG
                         + row * BROWP + seg * 16;
            cp16(dst, src, gv < NV ? 16 : 0);
        }
        asm volatile("cp.async.commit_group;" ::: "memory");
    };

    // prologue: first tile's chunks 0/1
    {
        int vb0 = ng * NT + wn * 32;
        loadB(vb0, 0, 0);
        loadB(vb0, 1, 1);
    }

    for (int nt = ng; nt < NNT; nt += NGP) {
        int vbase = nt * NT + wn * 32;
        int hasnext = (nt + NGP) < NNT;
        int vnext = (nt + NGP) * NT + wn * 32;

        float acc[4][4][4];
        #pragma unroll
        for (int a = 0; a < 4; a++)
            #pragma unroll
            for (int b = 0; b < 4; b++)
                #pragma unroll
                for (int c = 0; c < 4; c++) acc[a][b][c] = 0.f;

        #pragma unroll 1
        for (int c = 0; c < 8; c++) {
            if (c == 7 && !hasnext) {
                asm volatile("cp.async.wait_group 0;" ::: "memory");
            } else {
                asm volatile("cp.async.wait_group 1;" ::: "memory");
            }
            __syncwarp();

            int buf = c & 1;
            uint32_t bufH = warpB + buf * (2 * BSEG) + bThr;
            uint32_t bufL = bufH + BSEG;

            #pragma unroll
            for (int kk = 0; kk < 2; kk++) {
                int kg = c * 32 + kk * 16;
                int kl = kk * 32;
                uint32_t ah[4][4], al[4][4];
                #pragma unroll
                for (int mt = 0; mt < 4; mt++) {
                    ldsm4(ah[mt], aBase + mt * (16 * APITCH) + kg * 2);
                    ldsm4(al[mt], aBase + ASPLIT + mt * (16 * APITCH) + kg * 2);
                }
                uint32_t bh[2][4], bl[2][4];
                #pragma unroll
                for (int l = 0; l < 2; l++) {
                    ldsm4(bh[l], bufH + l * (16 * BROWP) + kl);
                    ldsm4(bl[l], bufL + l * (16 * BROWP) + kl);
                }
                #pragma unroll
                for (int mt = 0; mt < 4; mt++) {
                    #pragma unroll
                    for (int ntl = 0; ntl < 4; ntl++) {
                        int l = ntl >> 1, p = (ntl & 1) * 2;
                        uint32_t bhf[2] = {bh[l][p], bh[l][p + 1]};
                        uint32_t blf[2] = {bl[l][p], bl[l][p + 1]};
                        mma16816(acc[mt][ntl], ah[mt], bhf);
                        mma16816(acc[mt][ntl], ah[mt], blf);
                        mma16816(acc[mt][ntl], al[mt], bhf);
                    }
                }
            }
            if (c + 2 < 8) {
                loadB(vbase, c + 2, buf);        // same tile, freed buffer
            } else if (hasnext) {
                loadB(vnext, c + 2 - 8, buf);    // next tile chunk 0 (c=6) / 1 (c=7)
            }
        }

        // ---- epilogue (next tile's chunk 0/1 loads fly underneath) ----
        #pragma unroll
        for (int mt = 0; mt < 4; mt++) {
            int r0 = row0 + wm * 64 + mt * 16 + (lane >> 2);
            int r1 = r0 + 8;
            int tt0 = r0 >> 5, bb0 = r0 & 31;
            int tt1 = r1 >> 5, bb1 = r1 & 31;
            float* o0 = out + (long)bb0 * NTY * NV + (long)tt0 * NV;
            float* o1 = out + (long)bb1 * NTY * NV + (long)tt1 * NV;
            #pragma unroll
            for (int ntl = 0; ntl < 4; ntl++) {
                int cc = vbase + ntl * 8 + 2 * (lane & 3);
                if (cc < NV) {
                    float2 v0 = make_float2(acc[mt][ntl][0], acc[mt][ntl][1]);
                    float2 v1 = make_float2(acc[mt][ntl][2], acc[mt][ntl][3]);
                    *reinterpret_cast<float2*>(o0 + cc) = v0;
                    *reinterpret_cast<float2*>(o1 + cc) = v1;
                }
            }
        }
    }
}

// ---------------- launch ----------------------------------------------------
extern "C" void kernel_launch(void* const* d_in, const int* in_sizes, int n_in,
                              void* d_out, int out_size)
{
    const int*   enc_in = (const int*)d_in[0];
    const int*   dec_in = (const int*)d_in[1];
    const int*   len    = (const int*)d_in[2];
    const float* E      = (const float*)d_in[3];
    const float* W_enc  = (const float*)d_in[4];
    const float* b_enc  = (const float*)d_in[5];
    const float* W_dec  = (const float*)d_in[6];
    const float* b_dec  = (const float*)d_in[7];
    const float* W_proj = (const float*)d_in[8];
    float* out = (float*)d_out;

    cudaFuncSetAttribute(proj_mma, cudaFuncAttributeMaxDynamicSharedMemorySize,
                         PROJ_SMEM);

    init_state<<<64, 256>>>();

    wsplit<<<dim3((NV + 31) / 32, 8), 256>>>(W_proj);

    lstm_persist<<<NBLK, 256>>>(enc_in, dec_in, E, W_enc, b_enc,
                                W_dec, b_dec, len);

    proj_mma<<<dim3(NMT, NGP), 256, PROJ_SMEM>>>(out);
}